// round 7
// baseline (speedup 1.0000x reference)
#include <cuda_runtime.h>
#include <stdint.h>

// ---------------- static geometry ----------------
#define Bb   2
#define Ss   4096
#define Dd   2048
#define Hh   32
#define HDd  64
#define Tt   32
#define NTH  8
#define NTW  4
#define SCALE 0.125f  // 1/sqrt(64)

#define MM   (Bb*Ss)  // 8192
#define DD   ((size_t)Dd * Dd)

// ---------------- scratch ----------------
__device__ float g_Q[(size_t)MM * Dd];
__device__ float g_K[(size_t)MM * Dd];
__device__ float g_V[(size_t)MM * Dd];
__device__ float g_O[(size_t)MM * Dd];
__device__ float g_Xc[(size_t)MM * Dd];   // tf32-rounded X
__device__ float g_Wt[4 * DD];            // transposed + tf32-rounded weights [N][K]

// ---------------- helpers ----------------
__device__ __forceinline__ uint32_t tf32_bits(float x) {
    uint32_t u;
    asm("cvt.rna.tf32.f32 %0, %1;" : "=r"(u) : "f"(x));
    return u;
}
__device__ __forceinline__ float to_tf32(float x) {
    return __uint_as_float(tf32_bits(x));
}
__device__ __forceinline__ uint32_t smem_u32(const void* p) {
    uint32_t a;
    asm("{ .reg .u64 t; cvta.to.shared.u64 t, %1; cvt.u32.u64 %0, t; }"
        : "=r"(a) : "l"(p));
    return a;
}
__device__ __forceinline__ void cp16(uint32_t dst, const void* src) {
    asm volatile("cp.async.cg.shared.global [%0], [%1], 16;"
                 :: "r"(dst), "l"(src) : "memory");
}
__device__ __forceinline__ void cp_commit() {
    asm volatile("cp.async.commit_group;" ::: "memory");
}
template<int N>
__device__ __forceinline__ void cp_wait() {
    asm volatile("cp.async.wait_group %0;" :: "n"(N) : "memory");
}

// ---------------- prep kernels ----------------
__global__ __launch_bounds__(1024) void cvt_x_kernel(
    const float4* __restrict__ in, float4* __restrict__ out, int n4)
{
    int i = blockIdx.x * blockDim.x + threadIdx.x;
    if (i < n4) {
        float4 v = in[i];
        out[i] = make_float4(to_tf32(v.x), to_tf32(v.y), to_tf32(v.z), to_tf32(v.w));
    }
}

__global__ __launch_bounds__(256) void transpose_cvt4_kernel(
    const float* __restrict__ W0, const float* __restrict__ W1,
    const float* __restrict__ W2, const float* __restrict__ W3,
    float* __restrict__ Wt)
{
    __shared__ float t[32][33];
    const int z  = blockIdx.z;
    const float* W = (z == 0) ? W0 : (z == 1) ? W1 : (z == 2) ? W2 : W3;
    float* dst = Wt + (size_t)z * DD;
    const int bx = blockIdx.x * 32;  // n
    const int by = blockIdx.y * 32;  // k
    const int tx = threadIdx.x, ty = threadIdx.y;  // 32x8
#pragma unroll
    for (int r = 0; r < 32; r += 8)
        t[ty + r][tx] = W[(size_t)(by + ty + r) * Dd + bx + tx];
    __syncthreads();
#pragma unroll
    for (int r = 0; r < 32; r += 8)
        dst[(size_t)(bx + ty + r) * Dd + by + tx] = to_tf32(t[tx][ty + r]);
}

// ---------------- tf32 mma.sync GEMM, 256x128 block tile, 64x64 warp tile ----------------
// C[M,2048] = A[M,2048] @ Bt^T, A row-major [M][K], Bt row-major [N][K],
// both already tf32(RNA)-rounded. 256 threads, 8 warps (4 along M x 2 along N).
#define GBK 32
#define BM2 256
#define BN2 128
#define A_STAGE_FLOATS (BM2 * GBK)               // 8192
#define B_STAGE_FLOATS (BN2 * GBK)               // 4096
#define STAGE_BYTES ((A_STAGE_FLOATS + B_STAGE_FLOATS) * 4)  // 48 KB
#define NSTAGE 3
#define SMEM_GEMM_TOTAL (NSTAGE * STAGE_BYTES)   // 144 KB

__device__ __forceinline__ void gemm_fill_async(
    const float* __restrict__ A, const float* __restrict__ Bt,
    uint32_t sbase, int stage, int m0, int n0, int k0, int tid)
{
    const uint32_t sA = sbase + stage * STAGE_BYTES;
    const uint32_t sB = sA + A_STAGE_FLOATS * 4;
    // A: 256 rows x 8 chunks = 2048 cp16 -> 8 per thread
#pragma unroll
    for (int i = 0; i < 8; i++) {
        int idx = tid + i * 256;
        int row = idx >> 3;
        int c   = idx & 7;
        uint32_t phys = row * 128 + ((c ^ (row & 7)) << 4);
        cp16(sA + phys, &A[(size_t)(m0 + row) * Dd + k0 + c * 4]);
    }
    // B: 128 rows x 8 chunks = 1024 cp16 -> 4 per thread
#pragma unroll
    for (int i = 0; i < 4; i++) {
        int idx = tid + i * 256;
        int row = idx >> 3;
        int c   = idx & 7;
        uint32_t phys = row * 128 + ((c ^ (row & 7)) << 4);
        cp16(sB + phys, &Bt[(size_t)(n0 + row) * Dd + k0 + c * 4]);
    }
}

__global__ __launch_bounds__(256, 1) void tf32_gemm_async_kernel(
    const float* __restrict__ A, const float* __restrict__ Wt,
    float* __restrict__ C0, float* __restrict__ C1, float* __restrict__ C2)
{
    extern __shared__ char smem[];
    const uint32_t sbase = smem_u32(smem);
    const int tid  = threadIdx.x;
    const int wid  = tid >> 5;
    const int lane = tid & 31;
    const int g    = lane >> 2;   // 0..7
    const int t    = lane & 3;    // 0..3
    const int n0 = blockIdx.x * BN2;
    const int m0 = blockIdx.y * BM2;
    const int z  = blockIdx.z;

    const float* Bt = Wt + (size_t)z * DD;
    float* C = (z == 0) ? C0 : ((z == 1) ? C1 : C2);

    const int warp_m = (wid & 3) * 64;   // 4 warps down M
    const int warp_n = (wid >> 2) * 64;  // 2 warps across N

    float acc[4][8][4];
#pragma unroll
    for (int i = 0; i < 4; i++)
#pragma unroll
        for (int j = 0; j < 8; j++)
#pragma unroll
            for (int c = 0; c < 4; c++) acc[i][j][c] = 0.f;

    // prologue: stages 0,1 in flight
    gemm_fill_async(A, Bt, sbase, 0, m0, n0, 0, tid);
    cp_commit();
    gemm_fill_async(A, Bt, sbase, 1, m0, n0, GBK, tid);
    cp_commit();

    const int NCH = Dd / GBK;  // 64
    const int brow = (warp_n + g) * GBK;

    for (int ch = 0; ch < NCH; ch++) {
        if (ch < NCH - 2) cp_wait<1>(); else cp_wait<0>();
        __syncthreads();

        if (ch + 2 < NCH) {
            gemm_fill_async(A, Bt, sbase, (ch + 2) % NSTAGE, m0, n0,
                            (ch + 2) * GBK, tid);
            cp_commit();
        }

        const float* As = reinterpret_cast<const float*>(
            smem + (ch % NSTAGE) * STAGE_BYTES);
        const float* Bs = As + A_STAGE_FLOATS;

#pragma unroll
        for (int kk = 0; kk < GBK; kk += 8) {
            const int off1 = (((kk >> 2) ^ g) << 2) + t;
            const int off2 = off1 ^ 4;

            uint32_t af[4][4];
#pragma unroll
            for (int wm = 0; wm < 4; wm++) {
                const int rb = (warp_m + wm * 16 + g) * GBK;
                af[wm][0] = __float_as_uint(As[rb + off1]);
                af[wm][1] = __float_as_uint(As[rb + 8 * GBK + off1]);
                af[wm][2] = __float_as_uint(As[rb + off2]);
                af[wm][3] = __float_as_uint(As[rb + 8 * GBK + off2]);
            }
            uint32_t bf[8][2];
#pragma unroll
            for (int wn = 0; wn < 8; wn++) {
                const int rb = brow + wn * 8 * GBK;
                bf[wn][0] = __float_as_uint(Bs[rb + off1]);
                bf[wn][1] = __float_as_uint(Bs[rb + off2]);
            }
#pragma unroll
            for (int wm = 0; wm < 4; wm++)
#pragma unroll
                for (int wn = 0; wn < 8; wn++) {
                    asm volatile(
                        "mma.sync.aligned.m16n8k8.row.col.f32.tf32.tf32.f32 "
                        "{%0,%1,%2,%3},{%4,%5,%6,%7},{%8,%9},{%0,%1,%2,%3};"
                        : "+f"(acc[wm][wn][0]), "+f"(acc[wm][wn][1]),
                          "+f"(acc[wm][wn][2]), "+f"(acc[wm][wn][3])
                        : "r"(af[wm][0]), "r"(af[wm][1]),
                          "r"(af[wm][2]), "r"(af[wm][3]),
                          "r"(bf[wn][0]), "r"(bf[wn][1]));
                }
        }
    }

    // epilogue
#pragma unroll
    for (int wm = 0; wm < 4; wm++) {
        const int mb = m0 + warp_m + wm * 16;
#pragma unroll
        for (int wn = 0; wn < 8; wn++) {
            const int nb = n0 + warp_n + wn * 8 + 2 * t;
            *reinterpret_cast<float2*>(&C[(size_t)(mb + g) * Dd + nb]) =
                make_float2(acc[wm][wn][0], acc[wm][wn][1]);
            *reinterpret_cast<float2*>(&C[(size_t)(mb + g + 8) * Dd + nb]) =
                make_float2(acc[wm][wn][2], acc[wm][wn][3]);
        }
    }
}

// ---------------- tensor-core block-sparse sliding-tile attention ----------------
#define KS_STRIDE 68
#define VS_STRIDE 72

__global__ __launch_bounds__(256, 2) void attn_mma_kernel(
    const float* __restrict__ Q, const float* __restrict__ Kb,
    const float* __restrict__ Vb, float* __restrict__ O)
{
    __shared__ float Ks[64 * KS_STRIDE];
    __shared__ float Vs[64 * VS_STRIDE];

    const int tile = blockIdx.x;
    const int h    = blockIdx.y;
    const int b    = blockIdx.z;
    const int tid  = threadIdx.x;
    const int wid  = tid >> 5;
    const int lane = tid & 31;
    const int g    = lane >> 2;
    const int tg   = lane & 3;

    const int th_i = tile >> 2;
    const int tw_i = tile & 3;

    const int chc = min(max(th_i, 1), NTH - 1);
    const int cwc = min(max(tw_i, 1), NTW - 1);
    int kvt[4];
    kvt[0] = (chc - 1) * NTW + (cwc - 1);
    kvt[1] = (chc - 1) * NTW + cwc;
    kvt[2] = chc * NTW + (cwc - 1);
    kvt[3] = chc * NTW + cwc;

    const int qi0 = wid * 16 + g;
    const int qi1 = qi0 + 8;
    const int sq0 = (th_i * 8 + (qi0 >> 4)) * 64 + tw_i * 16 + (qi0 & 15);
    const int sq1 = (th_i * 8 + (qi1 >> 4)) * 64 + tw_i * 16 + (qi1 & 15);
    const size_t qrow0 = ((size_t)(b * Ss + sq0)) * Dd + h * HDd;
    const size_t qrow1 = ((size_t)(b * Ss + sq1)) * Dd + h * HDd;

    uint32_t qa[8][4];
#pragma unroll
    for (int kq = 0; kq < 8; kq++) {
        qa[kq][0] = tf32_bits(Q[qrow0 + 8 * kq + tg] * SCALE);
        qa[kq][1] = tf32_bits(Q[qrow1 + 8 * kq + tg] * SCALE);
        qa[kq][2] = tf32_bits(Q[qrow0 + 8 * kq + tg + 4] * SCALE);
        qa[kq][3] = tf32_bits(Q[qrow1 + 8 * kq + tg + 4] * SCALE);
    }

    float m0 = -1e30f, m1 = -1e30f, l0 = 0.f, l1 = 0.f;
    float oacc[8][4];
#pragma unroll
    for (int j = 0; j < 8; j++)
#pragma unroll
        for (int c = 0; c < 4; c++) oacc[j][c] = 0.f;

    for (int cidx = 0; cidx < 8; cidx++) {
        const int ktile = kvt[cidx >> 1];
        const int half  = cidx & 1;
        const int kth = ktile >> 2;
        const int ktw = ktile & 3;

        __syncthreads();
        for (int idx = tid; idx < 64 * 16; idx += 256) {
            int row = idx >> 4;
            int c4  = (idx & 15) * 4;
            int jj  = half * 64 + row;
            int rr  = jj >> 4;
            int cc  = jj & 15;
            int skv = (kth * 8 + rr) * 64 + (ktw * 16 + cc);
            size_t base = ((size_t)(b * Ss + skv)) * Dd + h * HDd + c4;
            float4 kv = *reinterpret_cast<const float4*>(Kb + base);
            float4 vv = *reinterpret_cast<const float4*>(Vb + base);
            *reinterpret_cast<float4*>(&Ks[row * KS_STRIDE + c4]) =
                make_float4(to_tf32(kv.x), to_tf32(kv.y), to_tf32(kv.z), to_tf32(kv.w));
            *reinterpret_cast<float4*>(&Vs[row * VS_STRIDE + c4]) =
                make_float4(to_tf32(vv.x), to_tf32(vv.y), to_tf32(vv.z), to_tf32(vv.w));
        }
        __syncthreads();

        float sacc[8][4];
#pragma unroll
        for (int j = 0; j < 8; j++)
#pragma unroll
            for (int c = 0; c < 4; c++) sacc[j][c] = 0.f;

#pragma unroll
        for (int kq = 0; kq < 8; kq++) {
#pragma unroll
            for (int jn = 0; jn < 8; jn++) {
                uint32_t b0 = __float_as_uint(Ks[(8 * jn + g) * KS_STRIDE + 8 * kq + tg]);
                uint32_t b1 = __float_as_uint(Ks[(8 * jn + g) * KS_STRIDE + 8 * kq + tg + 4]);
                asm volatile(
                    "mma.sync.aligned.m16n8k8.row.col.f32.tf32.tf32.f32 "
                    "{%0,%1,%2,%3},{%4,%5,%6,%7},{%8,%9},{%0,%1,%2,%3};"
                    : "+f"(sacc[jn][0]), "+f"(sacc[jn][1]),
                      "+f"(sacc[jn][2]), "+f"(sacc[jn][3])
                    : "r"(qa[kq][0]), "r"(qa[kq][1]),
                      "r"(qa[kq][2]), "r"(qa[kq][3]),
                      "r"(b0), "r"(b1));
            }
        }

        float mx0 = -1e30f, mx1 = -1e30f;
#pragma unroll
        for (int j = 0; j < 8; j++) {
            mx0 = fmaxf(mx0, fmaxf(sacc[j][0], sacc[j][1]));
            mx1 = fmaxf(mx1, fmaxf(sacc[j][2], sacc[j][3]));
        }
        mx0 = fmaxf(mx0, __shfl_xor_sync(0xffffffffu, mx0, 1));
        mx0 = fmaxf(mx0, __shfl_xor_sync(0xffffffffu, mx0, 2));
        mx1 = fmaxf(mx1, __shfl_xor_sync(0xffffffffu, mx1, 1));
        mx1 = fmaxf(mx1, __shfl_xor_sync(0xffffffffu, mx1, 2));

        float mn0 = fmaxf(m0, mx0);
        float mn1 = fmaxf(m1, mx1);
        float r0 = __expf(m0 - mn0);
        float r1 = __expf(m1 - mn1);
        m0 = mn0; m1 = mn1;
        l0 *= r0; l1 *= r1;
#pragma unroll
        for (int j = 0; j < 8; j++) {
            oacc[j][0] *= r0; oacc[j][1] *= r0;
            oacc[j][2] *= r1; oacc[j][3] *= r1;
        }
#pragma unroll
        for (int j = 0; j < 8; j++) {
            float p0 = __expf(sacc[j][0] - m0);
            float p1 = __expf(sacc[j][1] - m0);
            float p2 = __expf(sacc[j][2] - m1);
            float p3 = __expf(sacc[j][3] - m1);
            l0 += p0 + p1;
            l1 += p2 + p3;
            sacc[j][0] = to_tf32(p0);
            sacc[j][1] = to_tf32(p1);
            sacc[j][2] = to_tf32(p2);
            sacc[j][3] = to_tf32(p3);
        }

        const int src0 = (lane & ~3) | (tg >> 1);
        const int src1 = src0 + 2;
#pragma unroll
        for (int kk = 0; kk < 8; kk++) {
            float x0 = __shfl_sync(0xffffffffu, sacc[kk][0], src0);
            float x1 = __shfl_sync(0xffffffffu, sacc[kk][1], src0);
            float y0 = __shfl_sync(0xffffffffu, sacc[kk][0], src1);
            float y1 = __shfl_sync(0xffffffffu, sacc[kk][1], src1);
            float z0 = __shfl_sync(0xffffffffu, sacc[kk][2], src0);
            float z1 = __shfl_sync(0xffffffffu, sacc[kk][3], src0);
            float w0 = __shfl_sync(0xffffffffu, sacc[kk][2], src1);
            float w1 = __shfl_sync(0xffffffffu, sacc[kk][3], src1);
            uint32_t pa0 = __float_as_uint((tg & 1) ? x1 : x0);
            uint32_t pa1 = __float_as_uint((tg & 1) ? z1 : z0);
            uint32_t pa2 = __float_as_uint((tg & 1) ? y1 : y0);
            uint32_t pa3 = __float_as_uint((tg & 1) ? w1 : w0);
#pragma unroll
            for (int jn = 0; jn < 8; jn++) {
                uint32_t vb0 = __float_as_uint(Vs[(8 * kk + tg) * VS_STRIDE + 8 * jn + g]);
                uint32_t vb1 = __float_as_uint(Vs[(8 * kk + tg + 4) * VS_STRIDE + 8 * jn + g]);
                asm volatile(
                    "mma.sync.aligned.m16n8k8.row.col.f32.tf32.tf32.f32 "
                    "{%0,%1,%2,%3},{%4,%5,%6,%7},{%8,%9},{%0,%1,%2,%3};"
                    : "+f"(oacc[jn][0]), "+f"(oacc[jn][1]),
                      "+f"(oacc[jn][2]), "+f"(oacc[jn][3])
                    : "r"(pa0), "r"(pa1), "r"(pa2), "r"(pa3),
                      "r"(vb0), "r"(vb1));
            }
        }
    }

    l0 += __shfl_xor_sync(0xffffffffu, l0, 1);
    l0 += __shfl_xor_sync(0xffffffffu, l0, 2);
    l1 += __shfl_xor_sync(0xffffffffu, l1, 1);
    l1 += __shfl_xor_sync(0xffffffffu, l1, 2);
    const float inv0 = 1.f / l0;
    const float inv1 = 1.f / l1;

    float* orow0 = (float*)(O + qrow0);
    float* orow1 = (float*)(O + qrow1);
#pragma unroll
    for (int jn = 0; jn < 8; jn++) {
        int vd = 8 * jn + 2 * tg;
        *reinterpret_cast<float2*>(orow0 + vd) =
            make_float2(to_tf32(oacc[jn][0] * inv0), to_tf32(oacc[jn][1] * inv0));
        *reinterpret_cast<float2*>(orow1 + vd) =
            make_float2(to_tf32(oacc[jn][2] * inv1), to_tf32(oacc[jn][3] * inv1));
    }
}

// ---------------- launch ----------------
extern "C" void kernel_launch(void* const* d_in, const int* in_sizes, int n_in,
                              void* d_out, int out_size)
{
    const float* X  = (const float*)d_in[0];
    const float* Wq = (const float*)d_in[1];
    const float* Wk = (const float*)d_in[2];
    const float* Wv = (const float*)d_in[3];
    const float* Wo = (const float*)d_in[4];
    float* out = (float*)d_out;

    float *Qp, *Kp, *Vp, *Op, *Xc, *Wt;
    cudaGetSymbolAddress((void**)&Qp, g_Q);
    cudaGetSymbolAddress((void**)&Kp, g_K);
    cudaGetSymbolAddress((void**)&Vp, g_V);
    cudaGetSymbolAddress((void**)&Op, g_O);
    cudaGetSymbolAddress((void**)&Xc, g_Xc);
    cudaGetSymbolAddress((void**)&Wt, g_Wt);

    cudaFuncSetAttribute(tf32_gemm_async_kernel,
                         cudaFuncAttributeMaxDynamicSharedMemorySize, SMEM_GEMM_TOTAL);

    // prep: tf32-round X; transpose+round all 4 weights in one launch
    int n4 = (int)((size_t)MM * Dd / 4);
    cvt_x_kernel<<<(n4 + 1023) / 1024, 1024>>>((const float4*)X, (float4*)Xc, n4);
    dim3 tb(32, 8), tg4(64, 64, 4);
    transpose_cvt4_kernel<<<tg4, tb>>>(Wq, Wk, Wv, Wo, Wt);

    // fused Q/K/V projections
    dim3 gq(Dd / BN2, MM / BM2, 3);   // (16, 32, 3)
    tf32_gemm_async_kernel<<<gq, 256, SMEM_GEMM_TOTAL>>>(Xc, Wt, Qp, Kp, Vp);

    dim3 ga(Tt, Hh, Bb);
    attn_mma_kernel<<<ga, 256>>>(Qp, Kp, Vp, Op);

    // output projection
    dim3 gg(Dd / BN2, MM / BM2, 1);
    tf32_gemm_async_kernel<<<gg, 256, SMEM_GEMM_TOTAL>>>(Op, Wt + 3 * DD, out, out, out);
}

// round 8
// speedup vs baseline: 2.1438x; 2.1438x over previous
#include <cuda_runtime.h>
#include <cuda_fp16.h>
#include <stdint.h>

// ---------------- static geometry ----------------
#define Bb   2
#define Ss   4096
#define Dd   2048
#define Hh   32
#define HDd  64
#define NTH  8
#define NTW  4

#define MM   (Bb*Ss)  // 8192
#define DD   ((size_t)Dd * Dd)

// ---------------- scratch (fp16) ----------------
__device__ __half g_Qh[(size_t)MM * Dd];
__device__ __half g_Kh[(size_t)MM * Dd];
__device__ __half g_Vh[(size_t)MM * Dd];
__device__ __half g_Oh[(size_t)MM * Dd];
__device__ __half g_Xh[(size_t)MM * Dd];
__device__ __half g_Wh[4 * DD];          // transposed fp16 weights [N][K]

// ---------------- helpers ----------------
__device__ __forceinline__ uint32_t smem_u32(const void* p) {
    uint32_t a;
    asm("{ .reg .u64 t; cvta.to.shared.u64 t, %1; cvt.u32.u64 %0, t; }"
        : "=r"(a) : "l"(p));
    return a;
}
__device__ __forceinline__ void cp16(uint32_t dst, const void* src) {
    asm volatile("cp.async.cg.shared.global [%0], [%1], 16;"
                 :: "r"(dst), "l"(src) : "memory");
}
__device__ __forceinline__ void cp_commit() {
    asm volatile("cp.async.commit_group;" ::: "memory");
}
template<int N>
__device__ __forceinline__ void cp_wait() {
    asm volatile("cp.async.wait_group %0;" :: "n"(N) : "memory");
}
__device__ __forceinline__ uint32_t packh2(float a, float b) {
    __half2 h = __floats2half2_rn(a, b);
    return *reinterpret_cast<uint32_t*>(&h);
}

#define LDSM_X4(r0, r1, r2, r3, addr) \
    asm volatile("ldmatrix.sync.aligned.m8n8.x4.shared.b16 {%0,%1,%2,%3}, [%4];" \
                 : "=r"(r0), "=r"(r1), "=r"(r2), "=r"(r3) : "r"(addr))
#define LDSM_X4_T(r0, r1, r2, r3, addr) \
    asm volatile("ldmatrix.sync.aligned.m8n8.x4.trans.shared.b16 {%0,%1,%2,%3}, [%4];" \
                 : "=r"(r0), "=r"(r1), "=r"(r2), "=r"(r3) : "r"(addr))
#define HMMA16(acc, a, b0, b1) \
    asm volatile("mma.sync.aligned.m16n8k16.row.col.f32.f16.f16.f32 " \
                 "{%0,%1,%2,%3},{%4,%5,%6,%7},{%8,%9},{%0,%1,%2,%3};" \
                 : "+f"(acc[0]), "+f"(acc[1]), "+f"(acc[2]), "+f"(acc[3]) \
                 : "r"(a[0]), "r"(a[1]), "r"(a[2]), "r"(a[3]), "r"(b0), "r"(b1))

// ---------------- prep kernels ----------------
__global__ __launch_bounds__(1024) void cvt_x_h(
    const float4* __restrict__ in, uint2* __restrict__ out, int n4)
{
    int i = blockIdx.x * blockDim.x + threadIdx.x;
    if (i < n4) {
        float4 v = in[i];
        out[i] = make_uint2(packh2(v.x, v.y), packh2(v.z, v.w));
    }
}

__global__ __launch_bounds__(256) void transpose_cvt4_h(
    const float* __restrict__ W0, const float* __restrict__ W1,
    const float* __restrict__ W2, const float* __restrict__ W3,
    __half* __restrict__ Wh)
{
    __shared__ float t[32][33];
    const int z  = blockIdx.z;
    const float* W = (z == 0) ? W0 : (z == 1) ? W1 : (z == 2) ? W2 : W3;
    __half* dst = Wh + (size_t)z * DD;
    const int bx = blockIdx.x * 32;  // n
    const int by = blockIdx.y * 32;  // k
    const int tx = threadIdx.x, ty = threadIdx.y;
#pragma unroll
    for (int r = 0; r < 32; r += 8)
        t[ty + r][tx] = W[(size_t)(by + ty + r) * Dd + bx + tx];
    __syncthreads();
#pragma unroll
    for (int r = 0; r < 32; r += 8)
        dst[(size_t)(bx + ty + r) * Dd + by + tx] = __float2half_rn(t[tx][ty + r]);
}

// ---------------- fp16 GEMM: C[M,2048] = A[M,2048] @ Wt^T ----------------
// A fp16 [M][K], Wt fp16 [N][K]. 128x128 tile, BK=64, 256 thr, 8 warps (4m x 2n).
#define GBK 64
#define AST (128 * GBK * 2)      // 16384 B per operand
#define STB (2 * AST)            // 32768 B per stage
#define NST 3
#define SMEMT (NST * STB)        // 98304 B

__device__ __forceinline__ void hfill(
    const __half* __restrict__ A, const __half* __restrict__ Bt,
    uint32_t sbase, int stage, int m0, int n0, int k0, int tid)
{
    const uint32_t sA = sbase + stage * STB;
    const uint32_t sB = sA + AST;
#pragma unroll
    for (int i = 0; i < 4; i++) {
        int idx = tid + i * 256;
        int row = idx >> 3;
        int c   = idx & 7;
        uint32_t phys = row * 128 + ((c ^ (row & 7)) << 4);
        cp16(sA + phys, A + (size_t)(m0 + row) * Dd + k0 + c * 8);
    }
#pragma unroll
    for (int i = 0; i < 4; i++) {
        int idx = tid + i * 256;
        int row = idx >> 3;
        int c   = idx & 7;
        uint32_t phys = row * 128 + ((c ^ (row & 7)) << 4);
        cp16(sB + phys, Bt + (size_t)(n0 + row) * Dd + k0 + c * 8);
    }
}

__global__ __launch_bounds__(256, 2) void hgemm_kernel(
    const __half* __restrict__ A, const __half* __restrict__ Wh,
    void* C0, void* C1, void* C2, int out_f32)
{
    extern __shared__ char smem[];
    const uint32_t sbase = smem_u32(smem);
    const int tid  = threadIdx.x;
    const int wid  = tid >> 5;
    const int lane = tid & 31;
    const int g    = lane >> 2;
    const int t    = lane & 3;
    const int n0 = blockIdx.x * 128;
    const int m0 = blockIdx.y * 128;
    const int z  = blockIdx.z;

    const __half* Bt = Wh + (size_t)z * DD;
    void* Cv = (z == 0) ? C0 : ((z == 1) ? C1 : C2);

    const int warp_m = (wid & 3) * 32;
    const int warp_n = (wid >> 2) * 64;

    float acc[2][8][4];
#pragma unroll
    for (int i = 0; i < 2; i++)
#pragma unroll
        for (int j = 0; j < 8; j++)
#pragma unroll
            for (int c = 0; c < 4; c++) acc[i][j][c] = 0.f;

    hfill(A, Bt, sbase, 0, m0, n0, 0, tid);
    cp_commit();
    hfill(A, Bt, sbase, 1, m0, n0, GBK, tid);
    cp_commit();

    const int NCH = Dd / GBK;  // 32
    // lane-constant pieces of ldmatrix addressing
    const int lrow_a = ((lane >> 3) & 1) * 8 + (lane & 7);  // A/V row pattern
    const int lchk_a = (lane >> 4);                          // A/V chunk pattern
    const int lrow_b = ((lane >> 4) << 3) + (lane & 7);      // B/K row pattern
    const int lchk_b = ((lane >> 3) & 1);                    // B/K chunk pattern

    for (int ch = 0; ch < NCH; ch++) {
        if (ch < NCH - 1) cp_wait<1>(); else cp_wait<0>();
        __syncthreads();

        if (ch + 2 < NCH) {
            hfill(A, Bt, sbase, (ch + 2) % NST, m0, n0, (ch + 2) * GBK, tid);
            cp_commit();
        }

        const uint32_t sA = sbase + (ch % NST) * STB;
        const uint32_t sB = sA + AST;

#pragma unroll
        for (int ks = 0; ks < 4; ks++) {
            const int c0 = ks * 2;   // 16B-chunk base for this kstep

            uint32_t af[2][4];
#pragma unroll
            for (int wm = 0; wm < 2; wm++) {
                int row = warp_m + wm * 16 + lrow_a;
                int chk = c0 + lchk_a;
                uint32_t addr = sA + row * 128 + ((chk ^ (row & 7)) << 4);
                LDSM_X4(af[wm][0], af[wm][1], af[wm][2], af[wm][3], addr);
            }
#pragma unroll
            for (int p = 0; p < 4; p++) {
                int row = warp_n + p * 16 + lrow_b;
                int chk = c0 + lchk_b;
                uint32_t addr = sB + row * 128 + ((chk ^ (row & 7)) << 4);
                uint32_t b0, b1, b2, b3;
                LDSM_X4(b0, b1, b2, b3, addr);
#pragma unroll
                for (int wm = 0; wm < 2; wm++) {
                    HMMA16(acc[wm][2 * p],     af[wm], b0, b1);
                    HMMA16(acc[wm][2 * p + 1], af[wm], b2, b3);
                }
            }
        }
    }

    // epilogue
    if (out_f32) {
        float* C = (float*)Cv;
#pragma unroll
        for (int wm = 0; wm < 2; wm++) {
            const int mb = m0 + warp_m + wm * 16;
#pragma unroll
            for (int wn = 0; wn < 8; wn++) {
                const int nb = n0 + warp_n + wn * 8 + 2 * t;
                *reinterpret_cast<float2*>(&C[(size_t)(mb + g) * Dd + nb]) =
                    make_float2(acc[wm][wn][0], acc[wm][wn][1]);
                *reinterpret_cast<float2*>(&C[(size_t)(mb + g + 8) * Dd + nb]) =
                    make_float2(acc[wm][wn][2], acc[wm][wn][3]);
            }
        }
    } else {
        __half* C = (__half*)Cv;
#pragma unroll
        for (int wm = 0; wm < 2; wm++) {
            const int mb = m0 + warp_m + wm * 16;
#pragma unroll
            for (int wn = 0; wn < 8; wn++) {
                const int nb = n0 + warp_n + wn * 8 + 2 * t;
                *reinterpret_cast<uint32_t*>(&C[(size_t)(mb + g) * Dd + nb]) =
                    packh2(acc[wm][wn][0], acc[wm][wn][1]);
                *reinterpret_cast<uint32_t*>(&C[(size_t)(mb + g + 8) * Dd + nb]) =
                    packh2(acc[wm][wn][2], acc[wm][wn][3]);
            }
        }
    }
}

// ---------------- fp16 block-sparse sliding-tile attention ----------------
// One CTA (256 thr, 8 warps) per (b,h,t); warp owns 16 queries.
// 8 chunks of 64 keys, cp.async 3-stage. Smem per stage: Ks 8KB + Vs 8KB.
#define AKS  8192
#define AKST (2 * AKS)           // 16 KB per stage
#define ANST 3

__device__ __forceinline__ void afill(
    const __half* __restrict__ K, const __half* __restrict__ V,
    uint32_t sbase, int stage, int b, int h, int kth, int ktw, int half_, int tid)
{
    const uint32_t sK = sbase + stage * AKST;
    const uint32_t sV = sK + AKS;
#pragma unroll
    for (int i = 0; i < 2; i++) {
        int idx = tid + i * 256;
        int row = idx >> 3;         // key row 0..63
        int c   = idx & 7;          // 16B chunk (8 halves of hd)
        int jj  = half_ * 64 + row;
        int rr  = jj >> 4;
        int cc  = jj & 15;
        int skv = (kth * 8 + rr) * 64 + (ktw * 16 + cc);
        size_t gaddr = ((size_t)(b * Ss + skv)) * Dd + h * HDd + c * 8;
        uint32_t phys = row * 128 + ((c ^ (row & 7)) << 4);
        cp16(sK + phys, K + gaddr);
        cp16(sV + phys, V + gaddr);
    }
}

__global__ __launch_bounds__(256, 2) void attn_h_kernel(
    const __half* __restrict__ Q, const __half* __restrict__ Kh,
    const __half* __restrict__ Vh, __half* __restrict__ O)
{
    __shared__ char smem[ANST * AKST];   // 48 KB
    const uint32_t sbase = smem_u32(smem);

    const int tile = blockIdx.x;
    const int h    = blockIdx.y;
    const int b    = blockIdx.z;
    const int tid  = threadIdx.x;
    const int wid  = tid >> 5;
    const int lane = tid & 31;
    const int g    = lane >> 2;
    const int tg   = lane & 3;

    const int th_i = tile >> 2;
    const int tw_i = tile & 3;

    const int chc = min(max(th_i, 1), NTH - 1);
    const int cwc = min(max(tw_i, 1), NTW - 1);
    int kvt[4];
    kvt[0] = (chc - 1) * NTW + (cwc - 1);
    kvt[1] = (chc - 1) * NTW + cwc;
    kvt[2] = chc * NTW + (cwc - 1);
    kvt[3] = chc * NTW + cwc;

    const int qi0 = wid * 16 + g;
    const int qi1 = qi0 + 8;
    const int sq0 = (th_i * 8 + (qi0 >> 4)) * 64 + tw_i * 16 + (qi0 & 15);
    const int sq1 = (th_i * 8 + (qi1 >> 4)) * 64 + tw_i * 16 + (qi1 & 15);
    const size_t qrow0 = ((size_t)(b * Ss + sq0)) * Dd + h * HDd;  // half index
    const size_t qrow1 = ((size_t)(b * Ss + sq1)) * Dd + h * HDd;

    // Q fragments (scaled by 1/8 — exact in fp16)
    const __half2 qscale = __floats2half2_rn(0.125f, 0.125f);
    uint32_t qa[4][4];
#pragma unroll
    for (int ks = 0; ks < 4; ks++) {
        int kb = ks * 16;
        __half2 v0 = *reinterpret_cast<const __half2*>(&Q[qrow0 + kb + 2 * tg]);
        __half2 v1 = *reinterpret_cast<const __half2*>(&Q[qrow1 + kb + 2 * tg]);
        __half2 v2 = *reinterpret_cast<const __half2*>(&Q[qrow0 + kb + 8 + 2 * tg]);
        __half2 v3 = *reinterpret_cast<const __half2*>(&Q[qrow1 + kb + 8 + 2 * tg]);
        v0 = __hmul2(v0, qscale); v1 = __hmul2(v1, qscale);
        v2 = __hmul2(v2, qscale); v3 = __hmul2(v3, qscale);
        qa[ks][0] = *reinterpret_cast<uint32_t*>(&v0);
        qa[ks][1] = *reinterpret_cast<uint32_t*>(&v1);
        qa[ks][2] = *reinterpret_cast<uint32_t*>(&v2);
        qa[ks][3] = *reinterpret_cast<uint32_t*>(&v3);
    }

    // prologue fills (chunks 0,1)
    {
        int kt0 = kvt[0];
        afill(Kh, Vh, sbase, 0, b, h, kt0 >> 2, kt0 & 3, 0, tid);
        cp_commit();
        afill(Kh, Vh, sbase, 1, b, h, kt0 >> 2, kt0 & 3, 1, tid);
        cp_commit();
    }

    float m0 = -1e30f, m1 = -1e30f, l0 = 0.f, l1 = 0.f;
    float oacc[8][4];
#pragma unroll
    for (int j = 0; j < 8; j++)
#pragma unroll
        for (int c = 0; c < 4; c++) oacc[j][c] = 0.f;

    const int lrow_b = ((lane >> 4) << 3) + (lane & 7);  // K (non-trans) pattern
    const int lchk_b = ((lane >> 3) & 1);
    const int lrow_v = ((lane >> 3) & 1) * 8 + (lane & 7);  // V (trans) pattern
    const int lchk_v = (lane >> 4);

    for (int cidx = 0; cidx < 8; cidx++) {
        if (cidx < 7) cp_wait<1>(); else cp_wait<0>();
        __syncthreads();

        if (cidx + 2 < 8) {
            int kt = kvt[(cidx + 2) >> 1];
            afill(Kh, Vh, sbase, (cidx + 2) % ANST, b, h,
                  kt >> 2, kt & 3, (cidx + 2) & 1, tid);
            cp_commit();
        }

        const uint32_t sK = sbase + (cidx % ANST) * AKST;
        const uint32_t sV = sK + AKS;

        // ---- S = Q K^T ----
        float sacc[8][4];
#pragma unroll
        for (int j = 0; j < 8; j++)
#pragma unroll
            for (int c = 0; c < 4; c++) sacc[j][c] = 0.f;

#pragma unroll
        for (int ks = 0; ks < 4; ks++) {
            const int c0 = ks * 2;
#pragma unroll
            for (int p = 0; p < 4; p++) {
                int row = p * 16 + lrow_b;            // key row
                int chk = c0 + lchk_b;                // hd chunk
                uint32_t addr = sK + row * 128 + ((chk ^ (row & 7)) << 4);
                uint32_t k0, k1, k2, k3;
                LDSM_X4(k0, k1, k2, k3, addr);
                HMMA16(sacc[2 * p],     qa[ks], k0, k1);
                HMMA16(sacc[2 * p + 1], qa[ks], k2, k3);
            }
        }

        // ---- online softmax (fp32) ----
        float mx0 = -1e30f, mx1 = -1e30f;
#pragma unroll
        for (int j = 0; j < 8; j++) {
            mx0 = fmaxf(mx0, fmaxf(sacc[j][0], sacc[j][1]));
            mx1 = fmaxf(mx1, fmaxf(sacc[j][2], sacc[j][3]));
        }
        mx0 = fmaxf(mx0, __shfl_xor_sync(0xffffffffu, mx0, 1));
        mx0 = fmaxf(mx0, __shfl_xor_sync(0xffffffffu, mx0, 2));
        mx1 = fmaxf(mx1, __shfl_xor_sync(0xffffffffu, mx1, 1));
        mx1 = fmaxf(mx1, __shfl_xor_sync(0xffffffffu, mx1, 2));

        float mn0 = fmaxf(m0, mx0);
        float mn1 = fmaxf(m1, mx1);
        float r0 = __expf(m0 - mn0);
        float r1 = __expf(m1 - mn1);
        m0 = mn0; m1 = mn1;
        l0 *= r0; l1 *= r1;
#pragma unroll
        for (int j = 0; j < 8; j++) {
            oacc[j][0] *= r0; oacc[j][1] *= r0;
            oacc[j][2] *= r1; oacc[j][3] *= r1;
        }

        uint32_t pa[4][4];
#pragma unroll
        for (int mI = 0; mI < 4; mI++) {
            float p00 = __expf(sacc[2 * mI][0] - m0);
            float p01 = __expf(sacc[2 * mI][1] - m0);
            float p02 = __expf(sacc[2 * mI][2] - m1);
            float p03 = __expf(sacc[2 * mI][3] - m1);
            float p10 = __expf(sacc[2 * mI + 1][0] - m0);
            float p11 = __expf(sacc[2 * mI + 1][1] - m0);
            float p12 = __expf(sacc[2 * mI + 1][2] - m1);
            float p13 = __expf(sacc[2 * mI + 1][3] - m1);
            l0 += p00 + p01 + p10 + p11;
            l1 += p02 + p03 + p12 + p13;
            pa[mI][0] = packh2(p00, p01);   // A[g][2t,2t+1]       (tile 2m)
            pa[mI][1] = packh2(p02, p03);   // A[g+8][2t,2t+1]     (tile 2m)
            pa[mI][2] = packh2(p10, p11);   // A[g][2t+8,2t+9]     (tile 2m+1)
            pa[mI][3] = packh2(p12, p13);   // A[g+8][2t+8,2t+9]   (tile 2m+1)
        }

        // ---- O += P V ----
#pragma unroll
        for (int mI = 0; mI < 4; mI++) {
            const int kb = mI * 16;
#pragma unroll
            for (int p = 0; p < 4; p++) {
                int row = kb + lrow_v;                // key row
                int chk = 2 * p + lchk_v;             // hd chunk
                uint32_t addr = sV + row * 128 + ((chk ^ (row & 7)) << 4);
                uint32_t v0, v1, v2, v3;
                LDSM_X4_T(v0, v1, v2, v3, addr);
                HMMA16(oacc[2 * p],     pa[mI], v0, v1);
                HMMA16(oacc[2 * p + 1], pa[mI], v2, v3);
            }
        }
    }

    // ---- epilogue ----
    l0 += __shfl_xor_sync(0xffffffffu, l0, 1);
    l0 += __shfl_xor_sync(0xffffffffu, l0, 2);
    l1 += __shfl_xor_sync(0xffffffffu, l1, 1);
    l1 += __shfl_xor_sync(0xffffffffu, l1, 2);
    const float inv0 = 1.f / l0;
    const float inv1 = 1.f / l1;

#pragma unroll
    for (int jn = 0; jn < 8; jn++) {
        int vd = 8 * jn + 2 * tg;
        *reinterpret_cast<uint32_t*>(&O[qrow0 + vd]) =
            packh2(oacc[jn][0] * inv0, oacc[jn][1] * inv0);
        *reinterpret_cast<uint32_t*>(&O[qrow1 + vd]) =
            packh2(oacc[jn][2] * inv1, oacc[jn][3] * inv1);
    }
}

// ---------------- launch ----------------
extern "C" void kernel_launch(void* const* d_in, const int* in_sizes, int n_in,
                              void* d_out, int out_size)
{
    const float* X  = (const float*)d_in[0];
    const float* Wq = (const float*)d_in[1];
    const float* Wk = (const float*)d_in[2];
    const float* Wv = (const float*)d_in[3];
    const float* Wo = (const float*)d_in[4];
    float* out = (float*)d_out;

    __half *Qh, *Kh, *Vh, *Oh, *Xh, *Wh;
    cudaGetSymbolAddress((void**)&Qh, g_Qh);
    cudaGetSymbolAddress((void**)&Kh, g_Kh);
    cudaGetSymbolAddress((void**)&Vh, g_Vh);
    cudaGetSymbolAddress((void**)&Oh, g_Oh);
    cudaGetSymbolAddress((void**)&Xh, g_Xh);
    cudaGetSymbolAddress((void**)&Wh, g_Wh);

    cudaFuncSetAttribute(hgemm_kernel,
                         cudaFuncAttributeMaxDynamicSharedMemorySize, SMEMT);

    // prep
    int n4 = (int)((size_t)MM * Dd / 4);
    cvt_x_h<<<(n4 + 1023) / 1024, 1024>>>((const float4*)X, (uint2*)Xh, n4);
    dim3 tb(32, 8), tg4(64, 64, 4);
    transpose_cvt4_h<<<tg4, tb>>>(Wq, Wk, Wv, Wo, Wh);

    // fused Q/K/V projections (fp16 out)
    dim3 gq(Dd / 128, MM / 128, 3);
    hgemm_kernel<<<gq, 256, SMEMT>>>(Xh, Wh, Qh, Kh, Vh, 0);

    dim3 ga(32, Hh, Bb);
    attn_h_kernel<<<ga, 256>>>(Qh, Kh, Vh, Oh);

    // output projection (fp32 out)
    dim3 gg(Dd / 128, MM / 128, 1);
    hgemm_kernel<<<gg, 256, SMEMT>>>(Oh, Wh + 3 * DD, out, out, out, 1);
}